// round 13
// baseline (speedup 1.0000x reference)
#include <cuda_runtime.h>
#include <cstdint>

// ---------------------------------------------------------------------------
// SelfAttention: O = softmax( relu(XWq+bq) @ relu(XWk+bk)^T ) @ relu(XWv+bv)
// B=8, T=2048, D=DK=DV=1024, fp32 in/out.
// tf32 mma.sync GEMMs: 128x128 CTA tile, 256 threads, 32x64 warp tiles,
// 2 CTAs/SM, 3-stage cp.async, ldmatrix A-frags. Single stream.
//   NT (B in [N,K]): ldmatrix B-frags -> scores (Q@K^T)
//   NN (B in [K,N]): scalar B-frags   -> QKV (X@[Wq|Wk|Wv], 3-way split), PV
// Raw W reads with in-GEMM tf32(rna) rounding; no transpose/concat kernels.
// ---------------------------------------------------------------------------

#define BATCH 8
#define SEQ   2048
#define DIM   1024

// Scratch (device globals; no allocations allowed)
__device__ __align__(1024) float g_QKV[(size_t)BATCH * SEQ * 3 * DIM];
__device__ __align__(1024) float g_S  [(size_t)BATCH * SEQ * SEQ];

__device__ __forceinline__ uint32_t f2tf32(float x) {
    uint32_t y;
    asm("cvt.rna.tf32.f32 %0, %1;" : "=r"(y) : "f"(x));
    return y;
}
__device__ __forceinline__ uint32_t f2tf32_u(uint32_t xu) {
    uint32_t y;
    asm("cvt.rna.tf32.f32 %0, %1;" : "=r"(y) : "r"(xu));
    return y;
}

__device__ __forceinline__ void mma_tf32(float c[4], const uint32_t a[4], const uint32_t b[2]) {
    asm volatile(
        "mma.sync.aligned.m16n8k8.row.col.f32.tf32.tf32.f32 "
        "{%0,%1,%2,%3}, {%4,%5,%6,%7}, {%8,%9}, {%0,%1,%2,%3};"
        : "+f"(c[0]), "+f"(c[1]), "+f"(c[2]), "+f"(c[3])
        : "r"(a[0]), "r"(a[1]), "r"(a[2]), "r"(a[3]), "r"(b[0]), "r"(b[1]));
}

__device__ __forceinline__ void ldsm4(uint32_t& r0, uint32_t& r1, uint32_t& r2, uint32_t& r3,
                                      uint32_t saddr) {
    asm volatile("ldmatrix.sync.aligned.m8n8.x4.shared.b16 {%0,%1,%2,%3}, [%4];"
                 : "=r"(r0), "=r"(r1), "=r"(r2), "=r"(r3) : "r"(saddr));
}

__device__ __forceinline__ void cp_async16(void* smem_dst, const void* gsrc) {
    uint32_t d = (uint32_t)__cvta_generic_to_shared(smem_dst);
    asm volatile("cp.async.cg.shared.global [%0], [%1], 16;\n" :: "r"(d), "l"(gsrc));
}
__device__ __forceinline__ void cp_commit() {
    asm volatile("cp.async.commit_group;\n" ::: "memory");
}
template <int N>
__device__ __forceinline__ void cp_wait() {
    asm volatile("cp.async.wait_group %0;\n" :: "n"(N) : "memory");
}

// ---------------------------------------------------------------------------
// tf32 GEMM:
//  TRANS_B=true : C[M,N] = A[M,K] @ B[N,K]^T  (ldmatrix B-frags)
//  TRANS_B=false: C[M,N] = A[M,K] @ B[K,N]    (scalar B-frags)
// 3-way B/bias column split at ns1/ns2 (CTA-uniform select, cols rebased).
// CVT_A / CVT_B: round raw fp32 fragments to tf32(rna) post-load.
// Block 128x128x32, 256 threads (8 warps 4x2), warp tile 32x64, 3-stage cp.async.
// ---------------------------------------------------------------------------
template <bool TRANS_B, bool CVT_A, bool CVT_B, bool BIAS_RELU, bool ROUND_OUT>
__global__ __launch_bounds__(256, 2)
void gemm_kernel(const float* __restrict__ A,
                 const float* __restrict__ B0, const float* __restrict__ B1,
                 const float* __restrict__ B2,
                 const float* __restrict__ bias0, const float* __restrict__ bias1,
                 const float* __restrict__ bias2,
                 int ns1, int ns2, float* __restrict__ C,
                 int lda, int ldb, int ldc, int K,
                 size_t strideA, size_t strideB, size_t strideC)
{
    constexpr int BK = 32, STAGES = 3;
    constexpr int AST = 36;
    constexpr int BST = TRANS_B ? 36 : 136;
    constexpr int ATS = 128 * AST;
    constexpr int BTS = TRANS_B ? (128 * 36) : (32 * 136);
    constexpr int SSZ = ATS + BTS;

    extern __shared__ float sm[];

    A += (size_t)blockIdx.z * strideA;
    const int blockN = blockIdx.x * 128;
    const float* Bsel;
    const float* biasSel;
    int nOff;
    if (blockN < ns1)      { Bsel = B0; biasSel = bias0; nOff = blockN; }
    else if (blockN < ns2) { Bsel = B1; biasSel = bias1; nOff = blockN - ns1; }
    else                   { Bsel = B2; biasSel = bias2; nOff = blockN - ns2; }
    Bsel += (size_t)blockIdx.z * strideB;

    const int tid  = threadIdx.x;
    const int lane = tid & 31;
    const int warp = tid >> 5;
    const int wm0  = (warp >> 1) * 32;
    const int wn0  = (warp & 1) * 64;

    const int blockM = blockIdx.y * 128;

    const int qr = lane >> 2;
    const int qc = lane & 3;

    uint32_t offA[2], offB[4];
    {
        const int ar = wm0 + (lane & 15);
        const int ac = (lane >> 4) * 4;
        #pragma unroll
        for (int mt = 0; mt < 2; mt++)
            offA[mt] = (uint32_t)(((ar + mt * 16) * AST + ac) * 4);
        if (TRANS_B) {
            const int bsel = lane >> 4;
            const int br   = wn0 + bsel * 8 + (lane & 7);
            const int bc   = ((lane >> 3) & 1) * 4;
            #pragma unroll
            for (int ntp = 0; ntp < 4; ntp++)
                offB[ntp] = (uint32_t)(((br + ntp * 16) * BST + bc) * 4);
        }
    }
    const uint32_t smU32 = (uint32_t)__cvta_generic_to_shared(sm);

    float acc[2][8][4];
    #pragma unroll
    for (int i = 0; i < 2; i++)
        #pragma unroll
        for (int j = 0; j < 8; j++)
            #pragma unroll
            for (int v = 0; v < 4; v++) acc[i][j][v] = 0.0f;

    auto load_tile = [&](int stage, int k0) {
        float* Asd = sm + stage * SSZ;
        float* Bsd = Asd + ATS;
        const float* Ag = A + (size_t)blockM * lda + k0;
        #pragma unroll
        for (int p = 0; p < 4; p++) {
            int idx = tid + p * 256;
            int r   = idx >> 3;
            int c4  = idx & 7;
            cp_async16(Asd + r * AST + c4 * 4, Ag + (size_t)r * lda + c4 * 4);
        }
        if (TRANS_B) {
            const float* Bg = Bsel + (size_t)nOff * ldb + k0;
            #pragma unroll
            for (int p = 0; p < 4; p++) {
                int idx = tid + p * 256;
                int r   = idx >> 3;
                int c4  = idx & 7;
                cp_async16(Bsd + r * BST + c4 * 4, Bg + (size_t)r * ldb + c4 * 4);
            }
        } else {
            const float* Bg = Bsel + (size_t)k0 * ldb + nOff;
            #pragma unroll
            for (int p = 0; p < 4; p++) {
                int idx = tid + p * 256;
                int r   = idx >> 5;
                int c4  = idx & 31;
                cp_async16(Bsd + r * BST + c4 * 4, Bg + (size_t)r * ldb + c4 * 4);
            }
        }
    };

    const int KT = K / BK;

    load_tile(0, 0);   cp_commit();
    load_tile(1, BK);  cp_commit();

    for (int kt = 0; kt < KT; kt++) {
        cp_wait<1>();
        __syncthreads();

        if (kt + 2 < KT) load_tile((kt + 2) % STAGES, (kt + 2) * BK);
        cp_commit();

        const uint32_t aBase = smU32 + (uint32_t)((kt % STAGES) * SSZ) * 4u;
        const uint32_t bBase = aBase + (uint32_t)ATS * 4u;
        const uint32_t* BsuNN = (const uint32_t*)(sm + (kt % STAGES) * SSZ + ATS);

        #pragma unroll
        for (int ks = 0; ks < 4; ks++) {
            const uint32_t kOff = (uint32_t)(ks * 8 * 4);
            uint32_t fa[2][4], fb[8][2];
            #pragma unroll
            for (int mt = 0; mt < 2; mt++) {
                ldsm4(fa[mt][0], fa[mt][1], fa[mt][2], fa[mt][3],
                      aBase + offA[mt] + kOff);
                if (CVT_A) {
                    fa[mt][0] = f2tf32_u(fa[mt][0]);
                    fa[mt][1] = f2tf32_u(fa[mt][1]);
                    fa[mt][2] = f2tf32_u(fa[mt][2]);
                    fa[mt][3] = f2tf32_u(fa[mt][3]);
                }
            }
            if (TRANS_B) {
                #pragma unroll
                for (int ntp = 0; ntp < 4; ntp++)
                    ldsm4(fb[2 * ntp][0], fb[2 * ntp][1],
                          fb[2 * ntp + 1][0], fb[2 * ntp + 1][1],
                          bBase + offB[ntp] + kOff);
            } else {
                const int k0s = ks * 8 + qc;
                #pragma unroll
                for (int nt = 0; nt < 8; nt++) {
                    const int n = wn0 + nt * 8 + qr;
                    fb[nt][0] = BsuNN[k0s * BST + n];
                    fb[nt][1] = BsuNN[(k0s + 4) * BST + n];
                    if (CVT_B) {
                        fb[nt][0] = f2tf32_u(fb[nt][0]);
                        fb[nt][1] = f2tf32_u(fb[nt][1]);
                    }
                }
            }
            #pragma unroll
            for (int mt = 0; mt < 2; mt++)
                #pragma unroll
                for (int nt = 0; nt < 8; nt++)
                    mma_tf32(acc[mt][nt], fa[mt], fb[nt]);
        }
    }

    C += (size_t)blockIdx.z * strideC;
    #pragma unroll
    for (int mt = 0; mt < 2; mt++) {
        #pragma unroll
        for (int nt = 0; nt < 8; nt++) {
            int gm  = blockM + wm0 + mt * 16 + qr;
            int gnl = wn0 + nt * 8 + qc * 2;            // col within this CTA tile
            int gn  = blockN + gnl;
            float2 v0, v1;
            v0.x = acc[mt][nt][0]; v0.y = acc[mt][nt][1];
            v1.x = acc[mt][nt][2]; v1.y = acc[mt][nt][3];
            if (BIAS_RELU) {
                float2 bb = *reinterpret_cast<const float2*>(&biasSel[nOff + gnl]);
                v0.x = fmaxf(v0.x + bb.x, 0.0f);
                v0.y = fmaxf(v0.y + bb.y, 0.0f);
                v1.x = fmaxf(v1.x + bb.x, 0.0f);
                v1.y = fmaxf(v1.y + bb.y, 0.0f);
            }
            if (ROUND_OUT) {
                v0.x = __uint_as_float(f2tf32(v0.x));
                v0.y = __uint_as_float(f2tf32(v0.y));
                v1.x = __uint_as_float(f2tf32(v1.x));
                v1.y = __uint_as_float(f2tf32(v1.y));
            }
            *reinterpret_cast<float2*>(&C[(size_t)gm * ldc + gn]) = v0;
            *reinterpret_cast<float2*>(&C[(size_t)(gm + 8) * ldc + gn]) = v1;
        }
    }
}

// ---------------------------------------------------------------------------
// Row softmax over rows of length 2048 (float4 I/O); tf32-rounded output.
// ---------------------------------------------------------------------------
__global__ __launch_bounds__(256)
void softmax_kernel(float* __restrict__ S, int ncols)
{
    const size_t row = blockIdx.x;
    float4* p = reinterpret_cast<float4*>(S + row * (size_t)ncols);
    const int tid  = threadIdx.x;
    const int lane = tid & 31;
    const int warp = tid >> 5;

    __shared__ float red[8];

    float4 v[2];
    float m = -1e30f;
    #pragma unroll
    for (int i = 0; i < 2; i++) {
        v[i] = p[tid + i * 256];
        m = fmaxf(m, fmaxf(fmaxf(v[i].x, v[i].y), fmaxf(v[i].z, v[i].w)));
    }
    #pragma unroll
    for (int o = 16; o; o >>= 1) m = fmaxf(m, __shfl_xor_sync(0xffffffffu, m, o));
    if (lane == 0) red[warp] = m;
    __syncthreads();
    m = red[0];
    #pragma unroll
    for (int i = 1; i < 8; i++) m = fmaxf(m, red[i]);
    __syncthreads();

    float s = 0.0f;
    #pragma unroll
    for (int i = 0; i < 2; i++) {
        v[i].x = __expf(v[i].x - m);
        v[i].y = __expf(v[i].y - m);
        v[i].z = __expf(v[i].z - m);
        v[i].w = __expf(v[i].w - m);
        s += (v[i].x + v[i].y) + (v[i].z + v[i].w);
    }
    #pragma unroll
    for (int o = 16; o; o >>= 1) s += __shfl_xor_sync(0xffffffffu, s, o);
    if (lane == 0) red[warp] = s;
    __syncthreads();
    float tot = red[0];
    #pragma unroll
    for (int i = 1; i < 8; i++) tot += red[i];
    float inv = 1.0f / tot;
    #pragma unroll
    for (int i = 0; i < 2; i++) {
        float4 o;
        o.x = __uint_as_float(f2tf32(v[i].x * inv));
        o.y = __uint_as_float(f2tf32(v[i].y * inv));
        o.z = __uint_as_float(f2tf32(v[i].z * inv));
        o.w = __uint_as_float(f2tf32(v[i].w * inv));
        p[tid + i * 256] = o;
    }
}

// ---------------------------------------------------------------------------
// Launch (single stream)
// ---------------------------------------------------------------------------
extern "C" void kernel_launch(void* const* d_in, const int* in_sizes, int n_in,
                              void* d_out, int out_size)
{
    const float* X  = (const float*)d_in[0];
    const float* Wq = (const float*)d_in[1];
    const float* bq = (const float*)d_in[2];
    const float* Wk = (const float*)d_in[3];
    const float* bk = (const float*)d_in[4];
    const float* Wv = (const float*)d_in[5];
    const float* bv = (const float*)d_in[6];
    float* out = (float*)d_out;

    void *pQKV, *pS;
    cudaGetSymbolAddress(&pQKV, g_QKV);
    cudaGetSymbolAddress(&pS,   g_S);
    float* QKV = (float*)pQKV;   // [16384, 3072]: cols 0..1023 Q, 1024.. K, 2048.. V
    float* S   = (float*)pS;

    const int M_qkv = BATCH * SEQ;                       // 16384
    const int SMEM_NT = 3 * (128 * 36 + 128 * 36) * 4;   // 110592 B
    const int SMEM_NN = 3 * (128 * 36 + 32 * 136) * 4;   // 107520 B
    const int BIGN = 1 << 30;

    cudaFuncSetAttribute(gemm_kernel<false, true,  true,  true,  true>,
                         cudaFuncAttributeMaxDynamicSharedMemorySize, SMEM_NN);
    cudaFuncSetAttribute(gemm_kernel<true,  false, false, false, false>,
                         cudaFuncAttributeMaxDynamicSharedMemorySize, SMEM_NT);
    cudaFuncSetAttribute(gemm_kernel<false, false, false, false, false>,
                         cudaFuncAttributeMaxDynamicSharedMemorySize, SMEM_NN);

    // 1) fused QKV GEMM (NN, raw X + raw W 3-way split):
    //    QKV = relu(X @ [Wq|Wk|Wv] + [bq|bk|bv]), outputs tf32-rounded
    {
        dim3 gg(3 * DIM / 128, M_qkv / 128, 1);
        gemm_kernel<false, true, true, true, true><<<gg, 256, SMEM_NN>>>(
            X, Wq, Wk, Wv, bq, bk, bv, DIM, 2 * DIM, QKV,
            DIM, DIM, 3 * DIM, DIM, 0, 0, 0);
    }

    // 2) scores: S_b = Q_b @ K_b^T (NT)
    {
        dim3 gg(SEQ / 128, SEQ / 128, BATCH);
        gemm_kernel<true, false, false, false, false><<<gg, 256, SMEM_NT>>>(
            QKV, QKV + DIM, QKV + DIM, QKV + DIM, nullptr, nullptr, nullptr,
            BIGN, BIGN, S,
            3 * DIM, 3 * DIM, SEQ, DIM,
            (size_t)SEQ * 3 * DIM, (size_t)SEQ * 3 * DIM, (size_t)SEQ * SEQ);
    }

    // 3) softmax (tf32-rounded output)
    softmax_kernel<<<BATCH * SEQ, 256>>>(S, SEQ);

    // 4) PV: O_b = P_b @ V_b (NN, V in place inside QKV)
    {
        dim3 gg(DIM / 128, SEQ / 128, BATCH);
        gemm_kernel<false, false, false, false, false><<<gg, 256, SMEM_NN>>>(
            S, QKV + 2 * DIM, QKV + 2 * DIM, QKV + 2 * DIM, nullptr, nullptr, nullptr,
            BIGN, BIGN, out,
            SEQ, 3 * DIM, DIM, SEQ,
            (size_t)SEQ * SEQ, (size_t)SEQ * 3 * DIM, (size_t)SEQ * DIM);
    }
}

// round 15
// speedup vs baseline: 1.0900x; 1.0900x over previous
#include <cuda_runtime.h>
#include <cstdint>

// ---------------------------------------------------------------------------
// SelfAttention: O = softmax( relu(XWq+bq) @ relu(XWk+bk)^T ) @ relu(XWv+bv)
// B=8, T=2048, D=DK=DV=1024, fp32 in/out.
// tf32 mma.sync GEMMs: 128x128 CTA tile, 256 threads, 32x64 warp tiles,
// 2 CTAs/SM, 3-stage cp.async, ldmatrix A-frags. Single stream.
//   NT variant (B in [N,K]): ldmatrix B-frags   -> scores (Q@K^T)
//   NN variant (B in [K,N]): scalar  B-frags    -> QKV (X@Wcat), PV (P@V)
// W pre-rounded+concatenated by cat3_cvt (NN inner loop stays cvt-free).
// (R14 = revert to R11 anchor, the measured best at 1372.5us.)
// ---------------------------------------------------------------------------

#define BATCH 8
#define SEQ   2048
#define DIM   1024

// Scratch (device globals; no allocations allowed)
__device__ __align__(1024) float g_QKV[(size_t)BATCH * SEQ * 3 * DIM];
__device__ __align__(1024) float g_S  [(size_t)BATCH * SEQ * SEQ];
__device__ __align__(1024) float g_Wc [(size_t)DIM * 3 * DIM];   // [K=1024][N=3072]
__device__ __align__(1024) float g_b  [3 * DIM];

__device__ __forceinline__ uint32_t f2tf32(float x) {
    uint32_t y;
    asm("cvt.rna.tf32.f32 %0, %1;" : "=r"(y) : "f"(x));
    return y;
}
__device__ __forceinline__ uint32_t f2tf32_u(uint32_t xu) {
    uint32_t y;
    asm("cvt.rna.tf32.f32 %0, %1;" : "=r"(y) : "r"(xu));
    return y;
}

__device__ __forceinline__ void mma_tf32(float c[4], const uint32_t a[4], const uint32_t b[2]) {
    asm volatile(
        "mma.sync.aligned.m16n8k8.row.col.f32.tf32.tf32.f32 "
        "{%0,%1,%2,%3}, {%4,%5,%6,%7}, {%8,%9}, {%0,%1,%2,%3};"
        : "+f"(c[0]), "+f"(c[1]), "+f"(c[2]), "+f"(c[3])
        : "r"(a[0]), "r"(a[1]), "r"(a[2]), "r"(a[3]), "r"(b[0]), "r"(b[1]));
}

__device__ __forceinline__ void ldsm4(uint32_t& r0, uint32_t& r1, uint32_t& r2, uint32_t& r3,
                                      uint32_t saddr) {
    asm volatile("ldmatrix.sync.aligned.m8n8.x4.shared.b16 {%0,%1,%2,%3}, [%4];"
                 : "=r"(r0), "=r"(r1), "=r"(r2), "=r"(r3) : "r"(saddr));
}

__device__ __forceinline__ void cp_async16(void* smem_dst, const void* gsrc) {
    uint32_t d = (uint32_t)__cvta_generic_to_shared(smem_dst);
    asm volatile("cp.async.cg.shared.global [%0], [%1], 16;\n" :: "r"(d), "l"(gsrc));
}
__device__ __forceinline__ void cp_commit() {
    asm volatile("cp.async.commit_group;\n" ::: "memory");
}
template <int N>
__device__ __forceinline__ void cp_wait() {
    asm volatile("cp.async.wait_group %0;\n" :: "n"(N) : "memory");
}

// ---------------------------------------------------------------------------
// tf32 GEMM:
//  TRANS_B=true : C[M,N] = A[M,K] @ B[N,K]^T  (B row-major [N,K], ldmatrix)
//  TRANS_B=false: C[M,N] = A[M,K] @ B[K,N]    (B row-major [K,N], scalar LDS)
// CVT_A: A raw fp32, round fragments post-ldmatrix. Else inputs pre-rounded.
// Block 128x128x32, 256 threads (8 warps 4x2), warp tile 32x64, 3-stage cp.async.
// ---------------------------------------------------------------------------
template <bool TRANS_B, bool CVT_A, bool BIAS_RELU, bool ROUND_OUT>
__global__ __launch_bounds__(256, 2)
void gemm_kernel(const float* __restrict__ A, const float* __restrict__ B,
                 const float* __restrict__ bias, float* __restrict__ C,
                 int lda, int ldb, int ldc, int K,
                 size_t strideA, size_t strideB, size_t strideC)
{
    constexpr int BK = 32, STAGES = 3;
    constexpr int AST = 36;                              // A row stride (floats)
    constexpr int BST = TRANS_B ? 36 : 136;              // B row stride
    constexpr int ATS = 128 * AST;                       // A tile floats
    constexpr int BTS = TRANS_B ? (128 * 36) : (32 * 136);
    constexpr int SSZ = ATS + BTS;                       // one stage

    extern __shared__ float sm[];

    A += (size_t)blockIdx.z * strideA;
    B += (size_t)blockIdx.z * strideB;
    C += (size_t)blockIdx.z * strideC;

    const int tid  = threadIdx.x;
    const int lane = tid & 31;
    const int warp = tid >> 5;
    const int wm0  = (warp >> 1) * 32;      // 4 warps in M
    const int wn0  = (warp & 1) * 64;       // 2 warps in N

    const int blockM = blockIdx.y * 128;
    const int blockN = blockIdx.x * 128;

    const int qr = lane >> 2;   // 0..7
    const int qc = lane & 3;    // 0..3

    // ---- per-lane ldmatrix byte offsets ----
    uint32_t offA[2], offB[4];
    {
        const int ar = wm0 + (lane & 15);
        const int ac = (lane >> 4) * 4;
        #pragma unroll
        for (int mt = 0; mt < 2; mt++)
            offA[mt] = (uint32_t)(((ar + mt * 16) * AST + ac) * 4);
        if (TRANS_B) {
            const int bsel = lane >> 4;
            const int br   = wn0 + bsel * 8 + (lane & 7);
            const int bc   = ((lane >> 3) & 1) * 4;
            #pragma unroll
            for (int ntp = 0; ntp < 4; ntp++)
                offB[ntp] = (uint32_t)(((br + ntp * 16) * BST + bc) * 4);
        }
    }
    const uint32_t smU32 = (uint32_t)__cvta_generic_to_shared(sm);

    float acc[2][8][4];
    #pragma unroll
    for (int i = 0; i < 2; i++)
        #pragma unroll
        for (int j = 0; j < 8; j++)
            #pragma unroll
            for (int v = 0; v < 4; v++) acc[i][j][v] = 0.0f;

    // ---- async tile loader ----
    auto load_tile = [&](int stage, int k0) {
        float* Asd = sm + stage * SSZ;
        float* Bsd = Asd + ATS;
        const float* Ag = A + (size_t)blockM * lda + k0;
        #pragma unroll
        for (int p = 0; p < 4; p++) {
            int idx = tid + p * 256;        // 1024 chunks of 16B (A tile)
            int r   = idx >> 3;
            int c4  = idx & 7;
            cp_async16(Asd + r * AST + c4 * 4, Ag + (size_t)r * lda + c4 * 4);
        }
        if (TRANS_B) {
            const float* Bg = B + (size_t)blockN * ldb + k0;
            #pragma unroll
            for (int p = 0; p < 4; p++) {
                int idx = tid + p * 256;    // 1024 chunks: [n][k] rows
                int r   = idx >> 3;
                int c4  = idx & 7;
                cp_async16(Bsd + r * BST + c4 * 4, Bg + (size_t)r * ldb + c4 * 4);
            }
        } else {
            const float* Bg = B + (size_t)k0 * ldb + blockN;
            #pragma unroll
            for (int p = 0; p < 4; p++) {
                int idx = tid + p * 256;    // 1024 chunks: 32 k-rows x 32 n-chunks
                int r   = idx >> 5;
                int c4  = idx & 31;
                cp_async16(Bsd + r * BST + c4 * 4, Bg + (size_t)r * ldb + c4 * 4);
            }
        }
    };

    const int KT = K / BK;

    load_tile(0, 0);   cp_commit();
    load_tile(1, BK);  cp_commit();

    for (int kt = 0; kt < KT; kt++) {
        cp_wait<1>();
        __syncthreads();

        if (kt + 2 < KT) load_tile((kt + 2) % STAGES, (kt + 2) * BK);
        cp_commit();

        const uint32_t aBase = smU32 + (uint32_t)((kt % STAGES) * SSZ) * 4u;
        const uint32_t bBase = aBase + (uint32_t)ATS * 4u;
        const uint32_t* BsuNN = (const uint32_t*)(sm + (kt % STAGES) * SSZ + ATS);

        #pragma unroll
        for (int ks = 0; ks < 4; ks++) {
            const uint32_t kOff = (uint32_t)(ks * 8 * 4);
            uint32_t fa[2][4], fb[8][2];
            #pragma unroll
            for (int mt = 0; mt < 2; mt++) {
                ldsm4(fa[mt][0], fa[mt][1], fa[mt][2], fa[mt][3],
                      aBase + offA[mt] + kOff);
                if (CVT_A) {
                    fa[mt][0] = f2tf32_u(fa[mt][0]);
                    fa[mt][1] = f2tf32_u(fa[mt][1]);
                    fa[mt][2] = f2tf32_u(fa[mt][2]);
                    fa[mt][3] = f2tf32_u(fa[mt][3]);
                }
            }
            if (TRANS_B) {
                #pragma unroll
                for (int ntp = 0; ntp < 4; ntp++)
                    ldsm4(fb[2 * ntp][0], fb[2 * ntp][1],
                          fb[2 * ntp + 1][0], fb[2 * ntp + 1][1],
                          bBase + offB[ntp] + kOff);
            } else {
                const int k0s = ks * 8 + qc;
                #pragma unroll
                for (int nt = 0; nt < 8; nt++) {
                    const int n = wn0 + nt * 8 + qr;
                    fb[nt][0] = BsuNN[k0s * BST + n];
                    fb[nt][1] = BsuNN[(k0s + 4) * BST + n];
                }
            }
            #pragma unroll
            for (int mt = 0; mt < 2; mt++)
                #pragma unroll
                for (int nt = 0; nt < 8; nt++)
                    mma_tf32(acc[mt][nt], fa[mt], fb[nt]);
        }
    }

    // ---- epilogue ----
    #pragma unroll
    for (int mt = 0; mt < 2; mt++) {
        #pragma unroll
        for (int nt = 0; nt < 8; nt++) {
            int gm = blockM + wm0 + mt * 16 + qr;
            int gn = blockN + wn0 + nt * 8 + qc * 2;
            float2 v0, v1;
            v0.x = acc[mt][nt][0]; v0.y = acc[mt][nt][1];
            v1.x = acc[mt][nt][2]; v1.y = acc[mt][nt][3];
            if (BIAS_RELU) {
                float2 bb = *reinterpret_cast<const float2*>(&bias[gn]);
                v0.x = fmaxf(v0.x + bb.x, 0.0f);
                v0.y = fmaxf(v0.y + bb.y, 0.0f);
                v1.x = fmaxf(v1.x + bb.x, 0.0f);
                v1.y = fmaxf(v1.y + bb.y, 0.0f);
            }
            if (ROUND_OUT) {
                v0.x = __uint_as_float(f2tf32(v0.x));
                v0.y = __uint_as_float(f2tf32(v0.y));
                v1.x = __uint_as_float(f2tf32(v1.x));
                v1.y = __uint_as_float(f2tf32(v1.y));
            }
            *reinterpret_cast<float2*>(&C[(size_t)gm * ldc + gn]) = v0;
            *reinterpret_cast<float2*>(&C[(size_t)(gm + 8) * ldc + gn]) = v1;
        }
    }
}

// ---------------------------------------------------------------------------
// Concat Wq|Wk|Wv columns into Wc[k][0:3072], tf32(rna)-rounded. float4 I/O.
// ---------------------------------------------------------------------------
__global__ __launch_bounds__(256)
void cat3_cvt_kernel(const float4* __restrict__ A, const float4* __restrict__ B,
                     const float4* __restrict__ C, float4* __restrict__ out)
{
    int i = blockIdx.x * 256 + threadIdx.x;          // 0 .. 1024*768-1
    int k = i / 768;                                 // 768 float4 per output row
    int j = i - k * 768;
    float4 t;
    if (j < 256)      t = A[k * 256 + j];
    else if (j < 512) t = B[k * 256 + (j - 256)];
    else              t = C[k * 256 + (j - 512)];
    float4 o;
    o.x = __uint_as_float(f2tf32(t.x));
    o.y = __uint_as_float(f2tf32(t.y));
    o.z = __uint_as_float(f2tf32(t.z));
    o.w = __uint_as_float(f2tf32(t.w));
    out[i] = o;
}

// ---------------------------------------------------------------------------
// Row softmax over rows of length 2048 (float4 I/O); tf32-rounded output.
// ---------------------------------------------------------------------------
__global__ __launch_bounds__(256)
void softmax_kernel(float* __restrict__ S, int ncols)
{
    const size_t row = blockIdx.x;
    float4* p = reinterpret_cast<float4*>(S + row * (size_t)ncols);
    const int tid  = threadIdx.x;
    const int lane = tid & 31;
    const int warp = tid >> 5;

    __shared__ float red[8];

    float4 v[2];
    float m = -1e30f;
    #pragma unroll
    for (int i = 0; i < 2; i++) {
        v[i] = p[tid + i * 256];
        m = fmaxf(m, fmaxf(fmaxf(v[i].x, v[i].y), fmaxf(v[i].z, v[i].w)));
    }
    #pragma unroll
    for (int o = 16; o; o >>= 1) m = fmaxf(m, __shfl_xor_sync(0xffffffffu, m, o));
    if (lane == 0) red[warp] = m;
    __syncthreads();
    m = red[0];
    #pragma unroll
    for (int i = 1; i < 8; i++) m = fmaxf(m, red[i]);
    __syncthreads();

    float s = 0.0f;
    #pragma unroll
    for (int i = 0; i < 2; i++) {
        v[i].x = __expf(v[i].x - m);
        v[i].y = __expf(v[i].y - m);
        v[i].z = __expf(v[i].z - m);
        v[i].w = __expf(v[i].w - m);
        s += (v[i].x + v[i].y) + (v[i].z + v[i].w);
    }
    #pragma unroll
    for (int o = 16; o; o >>= 1) s += __shfl_xor_sync(0xffffffffu, s, o);
    if (lane == 0) red[warp] = s;
    __syncthreads();
    float tot = red[0];
    #pragma unroll
    for (int i = 1; i < 8; i++) tot += red[i];
    float inv = 1.0f / tot;
    #pragma unroll
    for (int i = 0; i < 2; i++) {
        float4 o;
        o.x = __uint_as_float(f2tf32(v[i].x * inv));
        o.y = __uint_as_float(f2tf32(v[i].y * inv));
        o.z = __uint_as_float(f2tf32(v[i].z * inv));
        o.w = __uint_as_float(f2tf32(v[i].w * inv));
        p[tid + i * 256] = o;
    }
}

// ---------------------------------------------------------------------------
// Launch (single stream)
// ---------------------------------------------------------------------------
extern "C" void kernel_launch(void* const* d_in, const int* in_sizes, int n_in,
                              void* d_out, int out_size)
{
    const float* X  = (const float*)d_in[0];
    const float* Wq = (const float*)d_in[1];
    const float* bq = (const float*)d_in[2];
    const float* Wk = (const float*)d_in[3];
    const float* bk = (const float*)d_in[4];
    const float* Wv = (const float*)d_in[5];
    const float* bv = (const float*)d_in[6];
    float* out = (float*)d_out;

    void *pQKV, *pS, *pWc, *pB;
    cudaGetSymbolAddress(&pQKV, g_QKV);
    cudaGetSymbolAddress(&pS,   g_S);
    cudaGetSymbolAddress(&pWc,  g_Wc);
    cudaGetSymbolAddress(&pB,   g_b);
    float* QKV = (float*)pQKV;   // [16384, 3072]: cols 0..1023 Q, 1024.. K, 2048.. V
    float* S   = (float*)pS;
    float* Wc  = (float*)pWc;    // [1024, 3072] = [Wq|Wk|Wv] cols, tf32-rounded
    float* bc  = (float*)pB;

    const int M_qkv = BATCH * SEQ;                       // 16384
    const int SMEM_NT = 3 * (128 * 36 + 128 * 36) * 4;   // 110592 B
    const int SMEM_NN = 3 * (128 * 36 + 32 * 136) * 4;   // 107520 B

    cudaFuncSetAttribute(gemm_kernel<false, true,  true,  true>,
                         cudaFuncAttributeMaxDynamicSharedMemorySize, SMEM_NN);
    cudaFuncSetAttribute(gemm_kernel<true,  false, false, false>,
                         cudaFuncAttributeMaxDynamicSharedMemorySize, SMEM_NT);
    cudaFuncSetAttribute(gemm_kernel<false, false, false, false>,
                         cudaFuncAttributeMaxDynamicSharedMemorySize, SMEM_NN);

    // 0) concat biases; concat + tf32-round W columns into Wc
    cudaMemcpyAsync(bc,           bq, DIM * 4, cudaMemcpyDeviceToDevice);
    cudaMemcpyAsync(bc + DIM,     bk, DIM * 4, cudaMemcpyDeviceToDevice);
    cudaMemcpyAsync(bc + 2 * DIM, bv, DIM * 4, cudaMemcpyDeviceToDevice);
    cat3_cvt_kernel<<<DIM * 768 / 256, 256>>>(
        (const float4*)Wq, (const float4*)Wk, (const float4*)Wv, (float4*)Wc);

    // 1) fused QKV GEMM (NN, raw X): QKV = relu(X @ Wc + bc), outputs tf32-rounded
    {
        dim3 gg(3 * DIM / 128, M_qkv / 128, 1);
        gemm_kernel<false, true, true, true><<<gg, 256, SMEM_NN>>>(
            X, Wc, bc, QKV, DIM, 3 * DIM, 3 * DIM, DIM, 0, 0, 0);
    }

    // 2) scores: S_b = Q_b @ K_b^T (NT), fp32 out
    {
        dim3 gg(SEQ / 128, SEQ / 128, BATCH);
        gemm_kernel<true, false, false, false><<<gg, 256, SMEM_NT>>>(
            QKV, QKV + DIM, nullptr, S, 3 * DIM, 3 * DIM, SEQ, DIM,
            (size_t)SEQ * 3 * DIM, (size_t)SEQ * 3 * DIM, (size_t)SEQ * SEQ);
    }

    // 3) softmax (tf32-rounded output)
    softmax_kernel<<<BATCH * SEQ, 256>>>(S, SEQ);

    // 4) O_b = P_b @ V_b (NN, V in place inside QKV)
    {
        dim3 gg(DIM / 128, SEQ / 128, BATCH);
        gemm_kernel<false, false, false, false><<<gg, 256, SMEM_NN>>>(
            S, QKV + 2 * DIM, nullptr, out, SEQ, 3 * DIM, DIM, SEQ,
            (size_t)SEQ * SEQ, (size_t)SEQ * 3 * DIM, (size_t)SEQ * DIM);
    }
}